// round 1
// baseline (speedup 1.0000x reference)
#include <cuda_runtime.h>

#define D 128
#define HDIM 512
#define MAXN 50048
#define LN_EPS 1e-5f

// ---------------- scratch (static device globals: alloc-free) ----------------
__device__ float g_z[(size_t)MAXN * D];        // 25.6 MB
__device__ float g_za[MAXN];
__device__ float g_hc[(size_t)MAXN * D];       // 25.6 MB
__device__ float g_hidden[(size_t)MAXN * HDIM];// 102.5 MB
__device__ int   g_row_start[MAXN + 1];

// ---------------- CSR offsets from sorted dst ----------------
__global__ void k_row_start(const int* __restrict__ dst, int E, int Nc) {
    int i = blockIdx.x * blockDim.x + threadIdx.x;
    if (i > E) return;
    int cur  = (i == E) ? Nc : dst[i];
    int prev = (i == 0) ? -1 : dst[i - 1];
    for (int n = prev + 1; n <= cur; n++) g_row_start[n] = i;
}

// ---------------- shared SGEMM core: C = A[Nrows,KDIM] @ B[BNcols,KDIM]^T ----
// block = 256 threads, tile 32 rows x 128 cols, 4x4 register microtile.
template <int KDIM, int BN>
__device__ __forceinline__ void gemm_core(const float* __restrict__ A,
                                          const float* __restrict__ B,
                                          int Nrows, int row0, int col0,
                                          float acc[4][4]) {
    constexpr int BM = 32, BK = 32;
    __shared__ float As[BK][BM + 4];
    __shared__ float Bs[BK][BN + 4];
    const int tid = threadIdx.x;
    const int tx = tid & 31, ty = tid >> 5;

    for (int k0 = 0; k0 < KDIM; k0 += BK) {
        // stage A tile (transposed to K-major)
        {
            int r  = tid >> 3;          // 0..31
            int kq = (tid & 7) * 4;     // 0..28
            float4 v = make_float4(0.f, 0.f, 0.f, 0.f);
            int grow = row0 + r;
            if (grow < Nrows)
                v = *(const float4*)(A + (size_t)grow * KDIM + k0 + kq);
            As[kq + 0][r] = v.x; As[kq + 1][r] = v.y;
            As[kq + 2][r] = v.z; As[kq + 3][r] = v.w;
        }
        // stage B tile (transposed to K-major)
        #pragma unroll
        for (int it = 0; it < BN / 32; it++) {
            int cr = (tid >> 3) + it * 32;   // 0..BN-1
            int kq = (tid & 7) * 4;
            float4 w = *(const float4*)(B + (size_t)(col0 + cr) * KDIM + k0 + kq);
            Bs[kq + 0][cr] = w.x; Bs[kq + 1][cr] = w.y;
            Bs[kq + 2][cr] = w.z; Bs[kq + 3][cr] = w.w;
        }
        __syncthreads();
        #pragma unroll
        for (int k = 0; k < BK; k++) {
            float4 a4 = *(const float4*)&As[k][ty * 4];
            float4 b4 = *(const float4*)&Bs[k][tx * 4];
            float av[4] = {a4.x, a4.y, a4.z, a4.w};
            float bv[4] = {b4.x, b4.y, b4.z, b4.w};
            #pragma unroll
            for (int i = 0; i < 4; i++)
                #pragma unroll
                for (int j = 0; j < 4; j++)
                    acc[i][j] += av[i] * bv[j];
        }
        __syncthreads();
    }
}

// ---------------- z = s @ W_fc^T, fused za = z @ a[:D] ----------------
__global__ void __launch_bounds__(256)
k_gemm_z(const float* __restrict__ s, const float* __restrict__ Wfc,
         const float* __restrict__ a_attn, int Nrows) {
    float acc[4][4] = {};
    int row0 = blockIdx.x * 32;
    gemm_core<D, 128>(s, Wfc, Nrows, row0, 0, acc);
    int tx = threadIdx.x & 31, ty = threadIdx.x >> 5;
    float4 av = *(const float4*)&a_attn[tx * 4];
    #pragma unroll
    for (int i = 0; i < 4; i++) {
        int grow = row0 + ty * 4 + i;
        if (grow >= Nrows) break;  // warp-uniform
        float4 zv = make_float4(acc[i][0], acc[i][1], acc[i][2], acc[i][3]);
        *(float4*)&g_z[(size_t)grow * D + tx * 4] = zv;
        float p = zv.x * av.x + zv.y * av.y + zv.z * av.z + zv.w * av.w;
        #pragma unroll
        for (int o = 16; o; o >>= 1) p += __shfl_xor_sync(0xffffffffu, p, o);
        if (tx == 0) g_za[grow] = p;
    }
}

// ---------------- warp-per-node segment softmax + aggregation + elu + c -----
__global__ void __launch_bounds__(256)
k_aggregate(const float* __restrict__ c, const int* __restrict__ src, int Nc) {
    int gw   = (blockIdx.x * blockDim.x + threadIdx.x) >> 5;
    int lane = threadIdx.x & 31;
    if (gw >= Nc) return;
    int beg = g_row_start[gw], end = g_row_start[gw + 1];
    float4 acc = make_float4(0.f, 0.f, 0.f, 0.f);
    if (beg < end) {
        float m = -1e30f;
        for (int i = beg + lane; i < end; i += 32) {
            float e = g_za[src[i]];
            e = e > 0.f ? e : 0.01f * e;
            m = fmaxf(m, e);
        }
        #pragma unroll
        for (int o = 16; o; o >>= 1) m = fmaxf(m, __shfl_xor_sync(0xffffffffu, m, o));
        float denom = 0.f;
        for (int i = beg; i < end; i++) {
            int sidx = __ldg(&src[i]);
            float e = g_za[sidx];
            e = e > 0.f ? e : 0.01f * e;
            float ex = __expf(e - m);
            denom += ex;
            float4 zr = *(const float4*)&g_z[(size_t)sidx * D + lane * 4];
            acc.x += ex * zr.x; acc.y += ex * zr.y;
            acc.z += ex * zr.z; acc.w += ex * zr.w;
        }
        float inv = 1.f / denom;
        acc.x *= inv; acc.y *= inv; acc.z *= inv; acc.w *= inv;
    }
    float4 cv = *(const float4*)&c[(size_t)gw * D + lane * 4];
    float4 h;
    h.x = (acc.x > 0.f ? acc.x : __expf(acc.x) - 1.f) + cv.x;
    h.y = (acc.y > 0.f ? acc.y : __expf(acc.y) - 1.f) + cv.y;
    h.z = (acc.z > 0.f ? acc.z : __expf(acc.z) - 1.f) + cv.z;
    h.w = (acc.w > 0.f ? acc.w : __expf(acc.w) - 1.f) + cv.w;
    *(float4*)&g_hc[(size_t)gw * D + lane * 4] = h;
}

// ---------------- hidden = relu(hc @ w1^T + b1) ----------------
__global__ void __launch_bounds__(256)
k_gemm_h1(const float* __restrict__ w1, const float* __restrict__ b1, int Nrows) {
    float acc[4][4] = {};
    int row0 = blockIdx.x * 32;
    int col0 = blockIdx.y * 128;
    gemm_core<D, 128>(g_hc, w1, Nrows, row0, col0, acc);
    int tx = threadIdx.x & 31, ty = threadIdx.x >> 5;
    float4 bv = *(const float4*)&b1[col0 + tx * 4];
    #pragma unroll
    for (int i = 0; i < 4; i++) {
        int grow = row0 + ty * 4 + i;
        if (grow >= Nrows) break;
        float4 o;
        o.x = fmaxf(acc[i][0] + bv.x, 0.f);
        o.y = fmaxf(acc[i][1] + bv.y, 0.f);
        o.z = fmaxf(acc[i][2] + bv.z, 0.f);
        o.w = fmaxf(acc[i][3] + bv.w, 0.f);
        *(float4*)&g_hidden[(size_t)grow * HDIM + col0 + tx * 4] = o;
    }
}

// --------- y = hidden @ w2^T + b2 + hc, then LayerNorm, fused out ---------
__global__ void __launch_bounds__(256)
k_gemm_h2_ln(const float* __restrict__ w2, const float* __restrict__ b2,
             const float* __restrict__ lng, const float* __restrict__ lnb,
             float* __restrict__ out, int Nrows) {
    float acc[4][4] = {};
    int row0 = blockIdx.x * 32;
    gemm_core<HDIM, 128>(g_hidden, w2, Nrows, row0, 0, acc);
    int tx = threadIdx.x & 31, ty = threadIdx.x >> 5;
    float4 bv = *(const float4*)&b2[tx * 4];
    float4 gv = *(const float4*)&lng[tx * 4];
    float4 bb = *(const float4*)&lnb[tx * 4];
    #pragma unroll
    for (int i = 0; i < 4; i++) {
        int grow = row0 + ty * 4 + i;
        if (grow >= Nrows) break;  // warp-uniform
        float4 hv = *(const float4*)&g_hc[(size_t)grow * D + tx * 4];
        float y0 = acc[i][0] + bv.x + hv.x;
        float y1 = acc[i][1] + bv.y + hv.y;
        float y2 = acc[i][2] + bv.z + hv.z;
        float y3 = acc[i][3] + bv.w + hv.w;
        float s1 = y0 + y1 + y2 + y3;
        float s2 = y0 * y0 + y1 * y1 + y2 * y2 + y3 * y3;
        #pragma unroll
        for (int o = 16; o; o >>= 1) {
            s1 += __shfl_xor_sync(0xffffffffu, s1, o);
            s2 += __shfl_xor_sync(0xffffffffu, s2, o);
        }
        float mean = s1 * (1.f / D);
        float var  = s2 * (1.f / D) - mean * mean;
        float rstd = rsqrtf(var + LN_EPS);
        float4 o4;
        o4.x = (y0 - mean) * rstd * gv.x + bb.x;
        o4.y = (y1 - mean) * rstd * gv.y + bb.y;
        o4.z = (y2 - mean) * rstd * gv.z + bb.z;
        o4.w = (y3 - mean) * rstd * gv.w + bb.w;
        *(float4*)&out[(size_t)grow * D + tx * 4] = o4;
    }
}

// ---------------- launch ----------------
extern "C" void kernel_launch(void* const* d_in, const int* in_sizes, int n_in,
                              void* d_out, int out_size) {
    const float* s      = (const float*)d_in[0];
    const float* c      = (const float*)d_in[1];
    const int*   src    = (const int*)d_in[2];
    const int*   dst    = (const int*)d_in[3];
    const float* Wfc    = (const float*)d_in[4];
    const float* a_attn = (const float*)d_in[5];
    const float* w1     = (const float*)d_in[6];
    const float* b1     = (const float*)d_in[7];
    const float* w2     = (const float*)d_in[8];
    const float* b2     = (const float*)d_in[9];
    const float* lng    = (const float*)d_in[10];
    const float* lnb    = (const float*)d_in[11];
    float* out = (float*)d_out;

    int Ns = in_sizes[0] / D;
    int Nc = in_sizes[1] / D;
    int E  = in_sizes[2];
    (void)n_in; (void)out_size;

    // 1. CSR offsets
    k_row_start<<<(E + 1 + 255) / 256, 256>>>(dst, E, Nc);
    // 2. z = s @ Wfc^T (+ za)
    k_gemm_z<<<(Ns + 31) / 32, 256>>>(s, Wfc, a_attn, Ns);
    // 3. segment softmax + aggregate + elu + residual c
    k_aggregate<<<(Nc * 32 + 255) / 256, 256>>>(c, src, Nc);
    // 4. hidden = relu(hc @ w1^T + b1)
    {
        dim3 g((Nc + 31) / 32, HDIM / 128);
        k_gemm_h1<<<g, 256>>>(w1, b1, Nc);
    }
    // 5. y = hidden @ w2^T + b2 + hc, LayerNorm -> out
    k_gemm_h2_ln<<<(Nc + 31) / 32, 256>>>(w2, b2, lng, lnb, out, Nc);
}

// round 2
// speedup vs baseline: 1.3237x; 1.3237x over previous
#include <cuda_runtime.h>

#define D 128
#define HDIM 512
#define MAXN 50048
#define LN_EPS 1e-5f
#define SMS 132   // smem row stride (mult of 4 for LDS.128 alignment)

// ---------------- scratch (static device globals: alloc-free) ----------------
__device__ float g_z[(size_t)MAXN * D];
__device__ float g_za[MAXN];
__device__ float g_hc[(size_t)MAXN * D];
__device__ float g_hidden[(size_t)MAXN * HDIM];
__device__ int   g_row_start[MAXN + 1];

// ---------------- CSR offsets from sorted dst ----------------
__global__ void k_row_start(const int* __restrict__ dst, int E, int Nc) {
    int i = blockIdx.x * blockDim.x + threadIdx.x;
    if (i > E) return;
    int cur  = (i == E) ? Nc : dst[i];
    int prev = (i == 0) ? -1 : dst[i - 1];
    for (int n = prev + 1; n <= cur; n++) g_row_start[n] = i;
}

// ------------ SGEMM core: C[128x128 tile] = A[rows,K] @ B[cols,K]^T ------------
// 256 threads, 8x8 microtile per thread with split fragments {x*4, 64+x*4}.
template <int KDIM>
__device__ __forceinline__ void gemm128_core(
    const float* __restrict__ A, const float* __restrict__ B,
    int Nrows, int row0, int col0, float (&acc)[8][8])
{
    constexpr int BK = 16;
    __shared__ float As[BK][SMS];
    __shared__ float Bs[BK][SMS];
    const int tid = threadIdx.x;
    const int tx = tid & 15, ty = tid >> 4;
    const int ar  = tid >> 2;            // 0..63 (second row = +64)
    const int akq = (tid & 3) * 4;       // 0,4,8,12

    const bool v0 = (row0 + ar)      < Nrows;
    const bool v1 = (row0 + ar + 64) < Nrows;
    const float* Ap0 = A + (size_t)(row0 + ar)      * KDIM + akq;
    const float* Ap1 = A + (size_t)(row0 + ar + 64) * KDIM + akq;
    const float* Bp0 = B + (size_t)(col0 + ar)      * KDIM + akq;
    const float* Bp1 = B + (size_t)(col0 + ar + 64) * KDIM + akq;

    const float4 f40 = make_float4(0.f, 0.f, 0.f, 0.f);
    float4 pa0 = v0 ? *(const float4*)Ap0 : f40;
    float4 pa1 = v1 ? *(const float4*)Ap1 : f40;
    float4 pb0 = *(const float4*)Bp0;
    float4 pb1 = *(const float4*)Bp1;

    int k0 = 0;
    for (;;) {
        As[akq+0][ar]    = pa0.x; As[akq+1][ar]    = pa0.y;
        As[akq+2][ar]    = pa0.z; As[akq+3][ar]    = pa0.w;
        As[akq+0][ar+64] = pa1.x; As[akq+1][ar+64] = pa1.y;
        As[akq+2][ar+64] = pa1.z; As[akq+3][ar+64] = pa1.w;
        Bs[akq+0][ar]    = pb0.x; Bs[akq+1][ar]    = pb0.y;
        Bs[akq+2][ar]    = pb0.z; Bs[akq+3][ar]    = pb0.w;
        Bs[akq+0][ar+64] = pb1.x; Bs[akq+1][ar+64] = pb1.y;
        Bs[akq+2][ar+64] = pb1.z; Bs[akq+3][ar+64] = pb1.w;
        __syncthreads();

        const bool more = (k0 + BK) < KDIM;
        if (more) {
            int ko = k0 + BK;
            pa0 = v0 ? *(const float4*)(Ap0 + ko) : f40;
            pa1 = v1 ? *(const float4*)(Ap1 + ko) : f40;
            pb0 = *(const float4*)(Bp0 + ko);
            pb1 = *(const float4*)(Bp1 + ko);
        }

        #pragma unroll
        for (int k = 0; k < BK; k++) {
            float4 a0 = *(const float4*)&As[k][ty * 4];
            float4 a1 = *(const float4*)&As[k][64 + ty * 4];
            float4 b0 = *(const float4*)&Bs[k][tx * 4];
            float4 b1 = *(const float4*)&Bs[k][64 + tx * 4];
            float av[8] = {a0.x,a0.y,a0.z,a0.w,a1.x,a1.y,a1.z,a1.w};
            float bv[8] = {b0.x,b0.y,b0.z,b0.w,b1.x,b1.y,b1.z,b1.w};
            #pragma unroll
            for (int i = 0; i < 8; i++)
                #pragma unroll
                for (int j = 0; j < 8; j++)
                    acc[i][j] += av[i] * bv[j];
        }
        if (!more) break;
        k0 += BK;
        __syncthreads();
    }
}

__device__ __forceinline__ int row_of(int row0, int ty, int i) {
    return row0 + ((i < 4) ? ty * 4 + i : 60 + ty * 4 + i);
}

// ---------------- z = s @ W_fc^T, fused za = z @ a[:D] ----------------
__global__ void __launch_bounds__(256, 2)
k_gemm_z(const float* __restrict__ s, const float* __restrict__ Wfc,
         const float* __restrict__ a_attn, int Nrows) {
    float acc[8][8] = {};
    const int row0 = blockIdx.x * 128;
    gemm128_core<D>(s, Wfc, Nrows, row0, 0, acc);
    const int tx = threadIdx.x & 15, ty = threadIdx.x >> 4;
    float4 av0 = *(const float4*)&a_attn[tx * 4];
    float4 av1 = *(const float4*)&a_attn[64 + tx * 4];
    #pragma unroll
    for (int i = 0; i < 8; i++) {
        int r = row_of(row0, ty, i);
        float4 z0 = make_float4(acc[i][0], acc[i][1], acc[i][2], acc[i][3]);
        float4 z1 = make_float4(acc[i][4], acc[i][5], acc[i][6], acc[i][7]);
        float p = z0.x*av0.x + z0.y*av0.y + z0.z*av0.z + z0.w*av0.w
                + z1.x*av1.x + z1.y*av1.y + z1.z*av1.z + z1.w*av1.w;
        #pragma unroll
        for (int o = 8; o; o >>= 1) p += __shfl_xor_sync(0xffffffffu, p, o);
        if (r < Nrows) {
            *(float4*)&g_z[(size_t)r * D + tx * 4]      = z0;
            *(float4*)&g_z[(size_t)r * D + 64 + tx * 4] = z1;
            if (tx == 0) g_za[r] = p;
        }
    }
}

// ------------- warp-per-node segment softmax + aggregation + elu + c -------------
__global__ void __launch_bounds__(256)
k_aggregate(const float* __restrict__ c, const int* __restrict__ src, int Nc) {
    int gw   = (blockIdx.x * blockDim.x + threadIdx.x) >> 5;
    int lane = threadIdx.x & 31;
    if (gw >= Nc) return;
    int beg = g_row_start[gw], end = g_row_start[gw + 1];
    float4 acc = make_float4(0.f, 0.f, 0.f, 0.f);
    if (beg < end) {
        float m = -1e30f;
        for (int i = beg + lane; i < end; i += 32) {
            float e = g_za[src[i]];
            e = e > 0.f ? e : 0.01f * e;
            m = fmaxf(m, e);
        }
        #pragma unroll
        for (int o = 16; o; o >>= 1) m = fmaxf(m, __shfl_xor_sync(0xffffffffu, m, o));
        float denom = 0.f;
        for (int i = beg; i < end; i++) {
            int sidx = __ldg(&src[i]);
            float e = g_za[sidx];
            e = e > 0.f ? e : 0.01f * e;
            float ex = __expf(e - m);
            denom += ex;
            float4 zr = *(const float4*)&g_z[(size_t)sidx * D + lane * 4];
            acc.x += ex * zr.x; acc.y += ex * zr.y;
            acc.z += ex * zr.z; acc.w += ex * zr.w;
        }
        float inv = 1.f / denom;
        acc.x *= inv; acc.y *= inv; acc.z *= inv; acc.w *= inv;
    }
    float4 cv = *(const float4*)&c[(size_t)gw * D + lane * 4];
    float4 h;
    h.x = (acc.x > 0.f ? acc.x : __expf(acc.x) - 1.f) + cv.x;
    h.y = (acc.y > 0.f ? acc.y : __expf(acc.y) - 1.f) + cv.y;
    h.z = (acc.z > 0.f ? acc.z : __expf(acc.z) - 1.f) + cv.z;
    h.w = (acc.w > 0.f ? acc.w : __expf(acc.w) - 1.f) + cv.w;
    *(float4*)&g_hc[(size_t)gw * D + lane * 4] = h;
}

// ---------------- hidden = relu(hc @ w1^T + b1) ----------------
__global__ void __launch_bounds__(256, 2)
k_gemm_h1(const float* __restrict__ w1, const float* __restrict__ b1, int Nrows) {
    float acc[8][8] = {};
    const int row0 = blockIdx.x * 128;
    const int col0 = blockIdx.y * 128;
    gemm128_core<D>(g_hc, w1, Nrows, row0, col0, acc);
    const int tx = threadIdx.x & 15, ty = threadIdx.x >> 4;
    float4 b0 = *(const float4*)&b1[col0 + tx * 4];
    float4 b1v = *(const float4*)&b1[col0 + 64 + tx * 4];
    #pragma unroll
    for (int i = 0; i < 8; i++) {
        int r = row_of(row0, ty, i);
        if (r >= Nrows) continue;
        float4 o0, o1;
        o0.x = fmaxf(acc[i][0] + b0.x, 0.f);
        o0.y = fmaxf(acc[i][1] + b0.y, 0.f);
        o0.z = fmaxf(acc[i][2] + b0.z, 0.f);
        o0.w = fmaxf(acc[i][3] + b0.w, 0.f);
        o1.x = fmaxf(acc[i][4] + b1v.x, 0.f);
        o1.y = fmaxf(acc[i][5] + b1v.y, 0.f);
        o1.z = fmaxf(acc[i][6] + b1v.z, 0.f);
        o1.w = fmaxf(acc[i][7] + b1v.w, 0.f);
        *(float4*)&g_hidden[(size_t)r * HDIM + col0 + tx * 4]      = o0;
        *(float4*)&g_hidden[(size_t)r * HDIM + col0 + 64 + tx * 4] = o1;
    }
}

// --------- y = hidden @ w2^T + b2 + hc, then LayerNorm, fused out ---------
__global__ void __launch_bounds__(256, 2)
k_gemm_h2_ln(const float* __restrict__ w2, const float* __restrict__ b2,
             const float* __restrict__ lng, const float* __restrict__ lnb,
             float* __restrict__ out, int Nrows) {
    float acc[8][8] = {};
    const int row0 = blockIdx.x * 128;
    gemm128_core<HDIM>(g_hidden, w2, Nrows, row0, 0, acc);
    const int tx = threadIdx.x & 15, ty = threadIdx.x >> 4;
    const float4 f40 = make_float4(0.f, 0.f, 0.f, 0.f);
    float4 bv0 = *(const float4*)&b2[tx * 4];
    float4 bv1 = *(const float4*)&b2[64 + tx * 4];
    float4 gv0 = *(const float4*)&lng[tx * 4];
    float4 gv1 = *(const float4*)&lng[64 + tx * 4];
    float4 bb0 = *(const float4*)&lnb[tx * 4];
    float4 bb1 = *(const float4*)&lnb[64 + tx * 4];
    #pragma unroll
    for (int i = 0; i < 8; i++) {
        int r = row_of(row0, ty, i);
        bool ok = r < Nrows;
        float4 h0 = ok ? *(const float4*)&g_hc[(size_t)r * D + tx * 4]      : f40;
        float4 h1 = ok ? *(const float4*)&g_hc[(size_t)r * D + 64 + tx * 4] : f40;
        float y[8];
        y[0] = acc[i][0] + bv0.x + h0.x;
        y[1] = acc[i][1] + bv0.y + h0.y;
        y[2] = acc[i][2] + bv0.z + h0.z;
        y[3] = acc[i][3] + bv0.w + h0.w;
        y[4] = acc[i][4] + bv1.x + h1.x;
        y[5] = acc[i][5] + bv1.y + h1.y;
        y[6] = acc[i][6] + bv1.z + h1.z;
        y[7] = acc[i][7] + bv1.w + h1.w;
        float s1 = 0.f, s2 = 0.f;
        #pragma unroll
        for (int j = 0; j < 8; j++) { s1 += y[j]; s2 += y[j] * y[j]; }
        #pragma unroll
        for (int o = 8; o; o >>= 1) {
            s1 += __shfl_xor_sync(0xffffffffu, s1, o);
            s2 += __shfl_xor_sync(0xffffffffu, s2, o);
        }
        float mean = s1 * (1.f / D);
        float var  = s2 * (1.f / D) - mean * mean;
        float rstd = rsqrtf(var + LN_EPS);
        if (ok) {
            float4 o0, o1;
            o0.x = (y[0] - mean) * rstd * gv0.x + bb0.x;
            o0.y = (y[1] - mean) * rstd * gv0.y + bb0.y;
            o0.z = (y[2] - mean) * rstd * gv0.z + bb0.z;
            o0.w = (y[3] - mean) * rstd * gv0.w + bb0.w;
            o1.x = (y[4] - mean) * rstd * gv1.x + bb1.x;
            o1.y = (y[5] - mean) * rstd * gv1.y + bb1.y;
            o1.z = (y[6] - mean) * rstd * gv1.z + bb1.z;
            o1.w = (y[7] - mean) * rstd * gv1.w + bb1.w;
            *(float4*)&out[(size_t)r * D + tx * 4]      = o0;
            *(float4*)&out[(size_t)r * D + 64 + tx * 4] = o1;
        }
    }
}

// ---------------- launch ----------------
extern "C" void kernel_launch(void* const* d_in, const int* in_sizes, int n_in,
                              void* d_out, int out_size) {
    const float* s      = (const float*)d_in[0];
    const float* c      = (const float*)d_in[1];
    const int*   src    = (const int*)d_in[2];
    const int*   dst    = (const int*)d_in[3];
    const float* Wfc    = (const float*)d_in[4];
    const float* a_attn = (const float*)d_in[5];
    const float* w1     = (const float*)d_in[6];
    const float* b1     = (const float*)d_in[7];
    const float* w2     = (const float*)d_in[8];
    const float* b2     = (const float*)d_in[9];
    const float* lng    = (const float*)d_in[10];
    const float* lnb    = (const float*)d_in[11];
    float* out = (float*)d_out;

    int Ns = in_sizes[0] / D;
    int Nc = in_sizes[1] / D;
    int E  = in_sizes[2];
    (void)n_in; (void)out_size;

    k_row_start<<<(E + 1 + 255) / 256, 256>>>(dst, E, Nc);
    k_gemm_z<<<(Ns + 127) / 128, 256>>>(s, Wfc, a_attn, Ns);
    k_aggregate<<<(Nc * 32 + 255) / 256, 256>>>(c, src, Nc);
    {
        dim3 g((Nc + 127) / 128, HDIM / 128);
        k_gemm_h1<<<g, 256>>>(w1, b1, Nc);
    }
    k_gemm_h2_ln<<<(Nc + 127) / 128, 256>>>(w2, b2, lng, lnb, out, Nc);
}

// round 3
// speedup vs baseline: 2.1175x; 1.5997x over previous
#include <cuda_runtime.h>
#include <cstdint>

#define D 128
#define HDIM 512
#define MAXN 50048
#define LN_EPS 1e-5f
#define BKS 24   // smem k-stride (≡8 mod 16 → conflict-free frag loads)

// ---------------- scratch ----------------
__device__ float g_z[(size_t)MAXN * D];
__device__ float g_za[MAXN];
__device__ float g_hc[(size_t)MAXN * D];
__device__ float g_hidden[(size_t)MAXN * HDIM];
__device__ int   g_row_start[MAXN + 1];

// ---------------- CSR offsets from sorted dst ----------------
__global__ void k_row_start(const int* __restrict__ dst, int E, int Nc) {
    int i = blockIdx.x * blockDim.x + threadIdx.x;
    if (i > E) return;
    int cur  = (i == E) ? Nc : dst[i];
    int prev = (i == 0) ? -1 : dst[i - 1];
    for (int n = prev + 1; n <= cur; n++) g_row_start[n] = i;
}

// ---------------- helpers ----------------
__device__ __forceinline__ uint32_t f2tf32(float f) {
    uint32_t o;
    asm("cvt.rna.tf32.f32 %0, %1;" : "=r"(o) : "f"(f));
    return o;
}
__device__ __forceinline__ void mma_tf32(float (&c)[4],
                                         const uint32_t (&a)[4],
                                         const uint32_t (&b)[2]) {
    asm volatile(
        "mma.sync.aligned.m16n8k8.row.col.f32.tf32.tf32.f32 "
        "{%0,%1,%2,%3}, {%4,%5,%6,%7}, {%8,%9}, {%0,%1,%2,%3};"
        : "+f"(c[0]), "+f"(c[1]), "+f"(c[2]), "+f"(c[3])
        : "r"(a[0]), "r"(a[1]), "r"(a[2]), "r"(a[3]), "r"(b[0]), "r"(b[1]));
}

// --------- tf32 MMA core: C[128x128] = A[rows,K] @ B[cols,K]^T ---------
// 256 thr, warp grid 4(m) x 2(n); warp tile 32x64; acc[2][8][4].
// K-permuted fragments: every frag load is a contiguous float2 from smem.
template <int KDIM>
__device__ __forceinline__ void mma_core(
    const float* __restrict__ A, const float* __restrict__ B,
    int Nrows, int row0, int col0,
    float (&acc)[2][8][4], float* As, float* Bs)
{
    const int tid  = threadIdx.x;
    const int wid  = tid >> 5, lane = tid & 31;
    const int wm = wid >> 1, wn = wid & 1;
    const int lr = lane >> 2, lc2 = (lane & 3) * 2;

    const int srow = tid >> 1;             // 0..127
    const int skq  = (tid & 1) * 8;        // 0 or 8
    const bool va = (row0 + srow) < Nrows;
    const float* Ap = A + (size_t)(row0 + srow) * KDIM + skq;
    const float* Bp = B + (size_t)(col0 + srow) * KDIM + skq;
    const float4 f40 = make_float4(0.f, 0.f, 0.f, 0.f);

    float4 pa0 = va ? *(const float4*)(Ap)     : f40;
    float4 pa1 = va ? *(const float4*)(Ap + 4) : f40;
    float4 pb0 = *(const float4*)(Bp);
    float4 pb1 = *(const float4*)(Bp + 4);

    constexpr int NT = KDIM / 16;
    #pragma unroll 1
    for (int kt = 0; kt < NT; kt++) {
        float* as = &As[srow * BKS + skq];
        as[0] = __uint_as_float(f2tf32(pa0.x));
        as[1] = __uint_as_float(f2tf32(pa0.y));
        as[2] = __uint_as_float(f2tf32(pa0.z));
        as[3] = __uint_as_float(f2tf32(pa0.w));
        as[4] = __uint_as_float(f2tf32(pa1.x));
        as[5] = __uint_as_float(f2tf32(pa1.y));
        as[6] = __uint_as_float(f2tf32(pa1.z));
        as[7] = __uint_as_float(f2tf32(pa1.w));
        float* bs = &Bs[srow * BKS + skq];
        bs[0] = __uint_as_float(f2tf32(pb0.x));
        bs[1] = __uint_as_float(f2tf32(pb0.y));
        bs[2] = __uint_as_float(f2tf32(pb0.z));
        bs[3] = __uint_as_float(f2tf32(pb0.w));
        bs[4] = __uint_as_float(f2tf32(pb1.x));
        bs[5] = __uint_as_float(f2tf32(pb1.y));
        bs[6] = __uint_as_float(f2tf32(pb1.z));
        bs[7] = __uint_as_float(f2tf32(pb1.w));
        __syncthreads();

        if (kt + 1 < NT) {
            int ko = (kt + 1) * 16;
            pa0 = va ? *(const float4*)(Ap + ko)     : f40;
            pa1 = va ? *(const float4*)(Ap + ko + 4) : f40;
            pb0 = *(const float4*)(Bp + ko);
            pb1 = *(const float4*)(Bp + ko + 4);
        }

        #pragma unroll
        for (int ks = 0; ks < 2; ks++) {
            uint32_t af[2][4];
            #pragma unroll
            for (int mf = 0; mf < 2; mf++) {
                int r = wm * 32 + mf * 16 + lr;
                float2 lo = *(const float2*)&As[r * BKS + ks * 8 + lc2];
                float2 hi = *(const float2*)&As[(r + 8) * BKS + ks * 8 + lc2];
                af[mf][0] = __float_as_uint(lo.x);
                af[mf][1] = __float_as_uint(hi.x);
                af[mf][2] = __float_as_uint(lo.y);
                af[mf][3] = __float_as_uint(hi.y);
            }
            #pragma unroll
            for (int nf = 0; nf < 8; nf++) {
                int n = wn * 64 + nf * 8 + lr;
                float2 bv = *(const float2*)&Bs[n * BKS + ks * 8 + lc2];
                uint32_t bf[2] = {__float_as_uint(bv.x), __float_as_uint(bv.y)};
                mma_tf32(acc[0][nf], af[0], bf);
                mma_tf32(acc[1][nf], af[1], bf);
            }
        }
        __syncthreads();
    }
}

// acc element (mf, nf, j): row = wm*32+mf*16+lr + (j>=2 ? 8:0),
//                          col = wn*64+nf*8+lc2 + (j&1)

// ---------------- z = s @ W_fc^T ----------------
__global__ void __launch_bounds__(256, 2)
k_gemm_z(const float* __restrict__ s, const float* __restrict__ Wfc, int Nrows) {
    __shared__ float As[128 * BKS], Bs[128 * BKS];
    float acc[2][8][4] = {};
    const int row0 = blockIdx.x * 128;
    mma_core<D>(s, Wfc, Nrows, row0, 0, acc, As, Bs);
    const int lane = threadIdx.x & 31, wid = threadIdx.x >> 5;
    const int wm = wid >> 1, wn = wid & 1;
    const int lr = lane >> 2, lc2 = (lane & 3) * 2;
    #pragma unroll
    for (int mf = 0; mf < 2; mf++)
        #pragma unroll
        for (int cp = 0; cp < 2; cp++) {
            int r = row0 + wm * 32 + mf * 16 + lr + cp * 8;
            if (r >= Nrows) continue;
            #pragma unroll
            for (int nf = 0; nf < 8; nf++) {
                float2 v = make_float2(acc[mf][nf][cp * 2], acc[mf][nf][cp * 2 + 1]);
                *(float2*)&g_z[(size_t)r * D + wn * 64 + nf * 8 + lc2] = v;
            }
        }
}

// ---------------- za = z @ a[:D] (warp per row) ----------------
__global__ void __launch_bounds__(256)
k_za(const float* __restrict__ a_attn, int Ns) {
    int gw = (blockIdx.x * blockDim.x + threadIdx.x) >> 5;
    int lane = threadIdx.x & 31;
    if (gw >= Ns) return;
    float4 zv = *(const float4*)&g_z[(size_t)gw * D + lane * 4];
    float4 av = *(const float4*)&a_attn[lane * 4];
    float p = zv.x * av.x + zv.y * av.y + zv.z * av.z + zv.w * av.w;
    #pragma unroll
    for (int o = 16; o; o >>= 1) p += __shfl_xor_sync(0xffffffffu, p, o);
    if (lane == 0) g_za[gw] = p;
}

// ------------- warp-per-node segment softmax + aggregation + elu + c -------------
__global__ void __launch_bounds__(256)
k_aggregate(const float* __restrict__ c, const int* __restrict__ src, int Nc) {
    int gw   = (blockIdx.x * blockDim.x + threadIdx.x) >> 5;
    int lane = threadIdx.x & 31;
    if (gw >= Nc) return;
    int beg = g_row_start[gw], end = g_row_start[gw + 1];
    float4 acc = make_float4(0.f, 0.f, 0.f, 0.f);
    if (beg < end) {
        float m = -1e30f;
        for (int i = beg + lane; i < end; i += 32) {
            float e = g_za[src[i]];
            e = e > 0.f ? e : 0.01f * e;
            m = fmaxf(m, e);
        }
        #pragma unroll
        for (int o = 16; o; o >>= 1) m = fmaxf(m, __shfl_xor_sync(0xffffffffu, m, o));
        float denom = 0.f;
        for (int i = beg; i < end; i++) {
            int sidx = __ldg(&src[i]);
            float e = g_za[sidx];
            e = e > 0.f ? e : 0.01f * e;
            float ex = __expf(e - m);
            denom += ex;
            float4 zr = *(const float4*)&g_z[(size_t)sidx * D + lane * 4];
            acc.x += ex * zr.x; acc.y += ex * zr.y;
            acc.z += ex * zr.z; acc.w += ex * zr.w;
        }
        float inv = 1.f / denom;
        acc.x *= inv; acc.y *= inv; acc.z *= inv; acc.w *= inv;
    }
    float4 cv = *(const float4*)&c[(size_t)gw * D + lane * 4];
    float4 h;
    h.x = (acc.x > 0.f ? acc.x : __expf(acc.x) - 1.f) + cv.x;
    h.y = (acc.y > 0.f ? acc.y : __expf(acc.y) - 1.f) + cv.y;
    h.z = (acc.z > 0.f ? acc.z : __expf(acc.z) - 1.f) + cv.z;
    h.w = (acc.w > 0.f ? acc.w : __expf(acc.w) - 1.f) + cv.w;
    *(float4*)&g_hc[(size_t)gw * D + lane * 4] = h;
}

// ---------------- hidden = relu(hc @ w1^T + b1) ----------------
__global__ void __launch_bounds__(256, 2)
k_gemm_h1(const float* __restrict__ w1, const float* __restrict__ b1, int Nrows) {
    __shared__ float As[128 * BKS], Bs[128 * BKS];
    float acc[2][8][4] = {};
    const int row0 = blockIdx.x * 128;
    const int col0 = blockIdx.y * 128;
    mma_core<D>(g_hc, w1, Nrows, row0, col0, acc, As, Bs);
    const int lane = threadIdx.x & 31, wid = threadIdx.x >> 5;
    const int wm = wid >> 1, wn = wid & 1;
    const int lr = lane >> 2, lc2 = (lane & 3) * 2;
    float2 bb[8];
    #pragma unroll
    for (int nf = 0; nf < 8; nf++)
        bb[nf] = *(const float2*)&b1[col0 + wn * 64 + nf * 8 + lc2];
    #pragma unroll
    for (int mf = 0; mf < 2; mf++)
        #pragma unroll
        for (int cp = 0; cp < 2; cp++) {
            int r = row0 + wm * 32 + mf * 16 + lr + cp * 8;
            if (r >= Nrows) continue;
            #pragma unroll
            for (int nf = 0; nf < 8; nf++) {
                float2 v;
                v.x = fmaxf(acc[mf][nf][cp * 2]     + bb[nf].x, 0.f);
                v.y = fmaxf(acc[mf][nf][cp * 2 + 1] + bb[nf].y, 0.f);
                *(float2*)&g_hidden[(size_t)r * HDIM + col0 + wn * 64 + nf * 8 + lc2] = v;
            }
        }
}

// --------- y = hidden @ w2^T + b2 + hc, LayerNorm -> out ---------
__global__ void __launch_bounds__(256, 2)
k_gemm_h2_ln(const float* __restrict__ w2, const float* __restrict__ b2,
             const float* __restrict__ lng, const float* __restrict__ lnb,
             float* __restrict__ out, int Nrows) {
    __shared__ float As[128 * BKS], Bs[128 * BKS];
    __shared__ float part1[2][128], part2[2][128];
    float acc[2][8][4] = {};
    const int row0 = blockIdx.x * 128;
    mma_core<HDIM>(g_hidden, w2, Nrows, row0, 0, acc, As, Bs);
    const int lane = threadIdx.x & 31, wid = threadIdx.x >> 5;
    const int wm = wid >> 1, wn = wid & 1;
    const int lr = lane >> 2, lc2 = (lane & 3) * 2;

    float2 bb[8], gg[8], be[8];
    #pragma unroll
    for (int nf = 0; nf < 8; nf++) {
        int cc = wn * 64 + nf * 8 + lc2;
        bb[nf] = *(const float2*)&b2[cc];
        gg[nf] = *(const float2*)&lng[cc];
        be[nf] = *(const float2*)&lnb[cc];
    }
    // pass 1: y = acc + b2 + hc (in place), per-row partial moments
    #pragma unroll
    for (int mf = 0; mf < 2; mf++)
        #pragma unroll
        for (int cp = 0; cp < 2; cp++) {
            int rl = wm * 32 + mf * 16 + lr + cp * 8;
            int r  = row0 + rl;
            bool ok = r < Nrows;
            float s1 = 0.f, s2 = 0.f;
            #pragma unroll
            for (int nf = 0; nf < 8; nf++) {
                float2 hv = ok ? *(const float2*)&g_hc[(size_t)r * D + wn * 64 + nf * 8 + lc2]
                               : make_float2(0.f, 0.f);
                float y0 = acc[mf][nf][cp * 2]     + bb[nf].x + hv.x;
                float y1 = acc[mf][nf][cp * 2 + 1] + bb[nf].y + hv.y;
                acc[mf][nf][cp * 2]     = y0;
                acc[mf][nf][cp * 2 + 1] = y1;
                s1 += y0 + y1;
                s2 += y0 * y0 + y1 * y1;
            }
            // sum over the 4 lanes sharing this row
            s1 += __shfl_xor_sync(0xffffffffu, s1, 1);
            s2 += __shfl_xor_sync(0xffffffffu, s2, 1);
            s1 += __shfl_xor_sync(0xffffffffu, s1, 2);
            s2 += __shfl_xor_sync(0xffffffffu, s2, 2);
            if ((lane & 3) == 0) { part1[wn][rl] = s1; part2[wn][rl] = s2; }
        }
    __syncthreads();
    // pass 2: combine across warp_n pair, normalize, store
    #pragma unroll
    for (int mf = 0; mf < 2; mf++)
        #pragma unroll
        for (int cp = 0; cp < 2; cp++) {
            int rl = wm * 32 + mf * 16 + lr + cp * 8;
            int r  = row0 + rl;
            float s1 = part1[0][rl] + part1[1][rl];
            float s2 = part2[0][rl] + part2[1][rl];
            float mean = s1 * (1.f / D);
            float var  = s2 * (1.f / D) - mean * mean;
            float rstd = rsqrtf(var + LN_EPS);
            if (r >= Nrows) continue;
            #pragma unroll
            for (int nf = 0; nf < 8; nf++) {
                float2 v;
                v.x = (acc[mf][nf][cp * 2]     - mean) * rstd * gg[nf].x + be[nf].x;
                v.y = (acc[mf][nf][cp * 2 + 1] - mean) * rstd * gg[nf].y + be[nf].y;
                *(float2*)&out[(size_t)r * D + wn * 64 + nf * 8 + lc2] = v;
            }
        }
}

// ---------------- launch ----------------
extern "C" void kernel_launch(void* const* d_in, const int* in_sizes, int n_in,
                              void* d_out, int out_size) {
    const float* s      = (const float*)d_in[0];
    const float* c      = (const float*)d_in[1];
    const int*   src    = (const int*)d_in[2];
    const int*   dst    = (const int*)d_in[3];
    const float* Wfc    = (const float*)d_in[4];
    const float* a_attn = (const float*)d_in[5];
    const float* w1     = (const float*)d_in[6];
    const float* b1     = (const float*)d_in[7];
    const float* w2     = (const float*)d_in[8];
    const float* b2     = (const float*)d_in[9];
    const float* lng    = (const float*)d_in[10];
    const float* lnb    = (const float*)d_in[11];
    float* out = (float*)d_out;

    int Ns = in_sizes[0] / D;
    int Nc = in_sizes[1] / D;
    int E  = in_sizes[2];
    (void)n_in; (void)out_size;

    k_row_start<<<(E + 1 + 255) / 256, 256>>>(dst, E, Nc);
    k_gemm_z<<<(Ns + 127) / 128, 256>>>(s, Wfc, Ns);
    k_za<<<(Ns * 32 + 255) / 256, 256>>>(a_attn, Ns);
    k_aggregate<<<(Nc * 32 + 255) / 256, 256>>>(c, src, Nc);
    {
        dim3 g((Nc + 127) / 128, HDIM / 128);
        k_gemm_h1<<<g, 256>>>(w1, b1, Nc);
    }
    k_gemm_h2_ln<<<(Nc + 127) / 128, 256>>>(w2, b2, lng, lnb, out, Nc);
}

// round 4
// speedup vs baseline: 2.2676x; 1.0709x over previous
#include <cuda_runtime.h>
#include <cstdint>

#define D 128
#define HDIM 512
#define MAXN 50048
#define LN_EPS 1e-5f
#define BKS 24   // smem k-stride for the cvt core (gemm_z)

// ---------------- scratch ----------------
__device__ float g_z[(size_t)MAXN * D];
__device__ float g_za[MAXN];
__device__ float g_hc[(size_t)MAXN * D];
__device__ float g_hc_t[(size_t)MAXN * D];      // tf32-rounded copy (GEMM A input)
__device__ float g_hidden[(size_t)MAXN * HDIM]; // stored tf32-rounded
__device__ float g_w1t[HDIM * D];
__device__ float g_w2t[D * HDIM];
__device__ int   g_row_start[MAXN + 1];

// ---------------- CSR offsets from sorted dst ----------------
__global__ void k_row_start(const int* __restrict__ dst, int E, int Nc) {
    int i = blockIdx.x * blockDim.x + threadIdx.x;
    if (i > E) return;
    int cur  = (i == E) ? Nc : dst[i];
    int prev = (i == 0) ? -1 : dst[i - 1];
    for (int n = prev + 1; n <= cur; n++) g_row_start[n] = i;
}

// ---------------- helpers ----------------
__device__ __forceinline__ uint32_t f2tf32(float f) {
    uint32_t o;
    asm("cvt.rna.tf32.f32 %0, %1;" : "=r"(o) : "f"(f));
    return o;
}
__device__ __forceinline__ float rnd_tf32(float f) { return __uint_as_float(f2tf32(f)); }

__device__ __forceinline__ void mma_tf32(float (&c)[4],
                                         const uint32_t (&a)[4],
                                         const uint32_t (&b)[2]) {
    asm volatile(
        "mma.sync.aligned.m16n8k8.row.col.f32.tf32.tf32.f32 "
        "{%0,%1,%2,%3}, {%4,%5,%6,%7}, {%8,%9}, {%0,%1,%2,%3};"
        : "+f"(c[0]), "+f"(c[1]), "+f"(c[2]), "+f"(c[3])
        : "r"(a[0]), "r"(a[1]), "r"(a[2]), "r"(a[3]), "r"(b[0]), "r"(b[1]));
}
__device__ __forceinline__ void cp16(uint32_t s, const float* g, int sz) {
    asm volatile("cp.async.ca.shared.global [%0], [%1], 16, %2;" :: "r"(s), "l"(g), "r"(sz));
}
#define CP_COMMIT() asm volatile("cp.async.commit_group;")
template <int N> __device__ __forceinline__ void cp_wait() {
    asm volatile("cp.async.wait_group %0;" :: "n"(N));
}

// ---------------- weight pre-rounding ----------------
__global__ void k_cvt_w(const float* __restrict__ w1, const float* __restrict__ w2) {
    int i = blockIdx.x * blockDim.x + threadIdx.x;
    if (i < HDIM * D) {
        g_w1t[i] = rnd_tf32(w1[i]);
        g_w2t[i] = rnd_tf32(w2[i]);
    }
}

// ========== cvt core (gemm_z only): converts while staging ==========
template <int KDIM>
__device__ __forceinline__ void mma_core_cvt(
    const float* __restrict__ A, const float* __restrict__ B,
    int Nrows, int row0, int col0,
    float (&acc)[2][8][4], float* As, float* Bs)
{
    const int tid  = threadIdx.x;
    const int wid  = tid >> 5, lane = tid & 31;
    const int wm = wid >> 1, wn = wid & 1;
    const int lr = lane >> 2, lc2 = (lane & 3) * 2;
    const int srow = tid >> 1;
    const int skq  = (tid & 1) * 8;
    const bool va = (row0 + srow) < Nrows;
    const float* Ap = A + (size_t)(row0 + srow) * KDIM + skq;
    const float* Bp = B + (size_t)(col0 + srow) * KDIM + skq;
    const float4 f40 = make_float4(0.f, 0.f, 0.f, 0.f);

    float4 pa0 = va ? *(const float4*)(Ap)     : f40;
    float4 pa1 = va ? *(const float4*)(Ap + 4) : f40;
    float4 pb0 = *(const float4*)(Bp);
    float4 pb1 = *(const float4*)(Bp + 4);

    constexpr int NT = KDIM / 16;
    #pragma unroll 1
    for (int kt = 0; kt < NT; kt++) {
        float* as = &As[srow * BKS + skq];
        as[0] = rnd_tf32(pa0.x); as[1] = rnd_tf32(pa0.y);
        as[2] = rnd_tf32(pa0.z); as[3] = rnd_tf32(pa0.w);
        as[4] = rnd_tf32(pa1.x); as[5] = rnd_tf32(pa1.y);
        as[6] = rnd_tf32(pa1.z); as[7] = rnd_tf32(pa1.w);
        float* bs = &Bs[srow * BKS + skq];
        bs[0] = rnd_tf32(pb0.x); bs[1] = rnd_tf32(pb0.y);
        bs[2] = rnd_tf32(pb0.z); bs[3] = rnd_tf32(pb0.w);
        bs[4] = rnd_tf32(pb1.x); bs[5] = rnd_tf32(pb1.y);
        bs[6] = rnd_tf32(pb1.z); bs[7] = rnd_tf32(pb1.w);
        __syncthreads();

        if (kt + 1 < NT) {
            int ko = (kt + 1) * 16;
            pa0 = va ? *(const float4*)(Ap + ko)     : f40;
            pa1 = va ? *(const float4*)(Ap + ko + 4) : f40;
            pb0 = *(const float4*)(Bp + ko);
            pb1 = *(const float4*)(Bp + ko + 4);
        }
        #pragma unroll
        for (int ks = 0; ks < 2; ks++) {
            uint32_t af[2][4];
            #pragma unroll
            for (int mf = 0; mf < 2; mf++) {
                int r = wm * 32 + mf * 16 + lr;
                float2 lo = *(const float2*)&As[r * BKS + ks * 8 + lc2];
                float2 hi = *(const float2*)&As[(r + 8) * BKS + ks * 8 + lc2];
                af[mf][0] = __float_as_uint(lo.x);
                af[mf][1] = __float_as_uint(hi.x);
                af[mf][2] = __float_as_uint(lo.y);
                af[mf][3] = __float_as_uint(hi.y);
            }
            #pragma unroll
            for (int nf = 0; nf < 8; nf++) {
                int n = wn * 64 + nf * 8 + lr;
                float2 bv = *(const float2*)&Bs[n * BKS + ks * 8 + lc2];
                uint32_t bf[2] = {__float_as_uint(bv.x), __float_as_uint(bv.y)};
                mma_tf32(acc[0][nf], af[0], bf);
                mma_tf32(acc[1][nf], af[1], bf);
            }
        }
        __syncthreads();
    }
}

// ========== pipelined core (pre-rounded operands, cp.async, 3-stage) ==========
template <int KDIM>
__device__ __forceinline__ void mma_core_pipe(
    const float* __restrict__ A, const float* __restrict__ B,
    int Nrows, int row0, int col0,
    float (&acc)[2][8][4], float* SA, float* SB)
{
    const int tid  = threadIdx.x;
    const int wid  = tid >> 5, lane = tid & 31;
    const int wm = wid >> 1, wn = wid & 1;
    const int lr = lane >> 2, lc2 = (lane & 3) * 2;
    const int srow = tid >> 1;
    const int skq  = (tid & 1) * 8;
    const int swst = ((srow >> 1) & 1) * 8;
    const int szA  = ((row0 + srow) < Nrows) ? 16 : 0;
    const float* Ap = A + (size_t)(row0 + srow) * KDIM + skq;
    const float* Bp = B + (size_t)(col0 + srow) * KDIM + skq;
    uint32_t sa = (uint32_t)__cvta_generic_to_shared(SA);
    uint32_t sb = (uint32_t)__cvta_generic_to_shared(SB);
    const uint32_t so0 = (uint32_t)(srow * 16 + (skq ^ swst)) * 4u;
    const uint32_t so1 = (uint32_t)(srow * 16 + ((skq + 4) ^ swst)) * 4u;
    constexpr int NT = KDIM / 16;

    auto stage = [&](int st, int kt) {
        uint32_t ao = sa + (uint32_t)st * 8192u;
        uint32_t bo = sb + (uint32_t)st * 8192u;
        const float* a = Ap + kt * 16;
        const float* b = Bp + kt * 16;
        cp16(ao + so0, a,     szA);
        cp16(ao + so1, a + 4, szA);
        cp16(bo + so0, b,     16);
        cp16(bo + so1, b + 4, 16);
        CP_COMMIT();
    };
    stage(0, 0);
    stage(1, 1 < NT ? 1 : 0);

    const int fsw = ((lr >> 1) & 1) * 8;
    #pragma unroll 1
    for (int kt = 0; kt < NT; kt++) {
        if (kt + 1 < NT) cp_wait<1>(); else cp_wait<0>();
        __syncthreads();
        if (kt + 2 < NT) stage((kt + 2) % 3, kt + 2);
        const float* as = SA + (kt % 3) * 2048;
        const float* bs = SB + (kt % 3) * 2048;
        #pragma unroll
        for (int ks = 0; ks < 2; ks++) {
            const int cc = (ks * 8 + lc2) ^ fsw;
            uint32_t af[2][4];
            #pragma unroll
            for (int mf = 0; mf < 2; mf++) {
                int r = wm * 32 + mf * 16 + lr;
                float2 lo = *(const float2*)&as[r * 16 + cc];
                float2 hi = *(const float2*)&as[(r + 8) * 16 + cc];
                af[mf][0] = __float_as_uint(lo.x);
                af[mf][1] = __float_as_uint(hi.x);
                af[mf][2] = __float_as_uint(lo.y);
                af[mf][3] = __float_as_uint(hi.y);
            }
            #pragma unroll
            for (int nf = 0; nf < 8; nf++) {
                int n = wn * 64 + nf * 8 + lr;
                float2 bv = *(const float2*)&bs[n * 16 + cc];
                uint32_t bf[2] = {__float_as_uint(bv.x), __float_as_uint(bv.y)};
                mma_tf32(acc[0][nf], af[0], bf);
                mma_tf32(acc[1][nf], af[1], bf);
            }
        }
    }
    __syncthreads();
}

// ---------------- z = s @ W_fc^T, fused za ----------------
__global__ void __launch_bounds__(256, 2)
k_gemm_z(const float* __restrict__ s, const float* __restrict__ Wfc,
         const float* __restrict__ a_attn, int Nrows) {
    __shared__ float As[128 * BKS], Bs[128 * BKS];
    __shared__ float zap[2][128];
    float acc[2][8][4] = {};
    const int row0 = blockIdx.x * 128;
    mma_core_cvt<D>(s, Wfc, Nrows, row0, 0, acc, As, Bs);
    const int lane = threadIdx.x & 31, wid = threadIdx.x >> 5;
    const int wm = wid >> 1, wn = wid & 1;
    const int lr = lane >> 2, lc2 = (lane & 3) * 2;
    float2 av[8];
    #pragma unroll
    for (int nf = 0; nf < 8; nf++)
        av[nf] = *(const float2*)&a_attn[wn * 64 + nf * 8 + lc2];
    #pragma unroll
    for (int mf = 0; mf < 2; mf++)
        #pragma unroll
        for (int cp = 0; cp < 2; cp++) {
            int rl = wm * 32 + mf * 16 + lr + cp * 8;
            int r  = row0 + rl;
            float p = 0.f;
            #pragma unroll
            for (int nf = 0; nf < 8; nf++) {
                p += acc[mf][nf][cp * 2] * av[nf].x + acc[mf][nf][cp * 2 + 1] * av[nf].y;
                if (r < Nrows) {
                    float2 v = make_float2(acc[mf][nf][cp * 2], acc[mf][nf][cp * 2 + 1]);
                    *(float2*)&g_z[(size_t)r * D + wn * 64 + nf * 8 + lc2] = v;
                }
            }
            p += __shfl_xor_sync(0xffffffffu, p, 1);
            p += __shfl_xor_sync(0xffffffffu, p, 2);
            if ((lane & 3) == 0) zap[wn][rl] = p;
        }
    __syncthreads();
    if (wn == 0 && (lane & 3) == 0) {
        #pragma unroll
        for (int mf = 0; mf < 2; mf++)
            #pragma unroll
            for (int cp = 0; cp < 2; cp++) {
                int rl = wm * 32 + mf * 16 + lr + cp * 8;
                int r  = row0 + rl;
                if (r < Nrows) g_za[r] = zap[0][rl] + zap[1][rl];
            }
    }
}

// ------- warp-per-node segment softmax + aggregation (x2 unroll) + elu + c -------
__global__ void __launch_bounds__(256)
k_aggregate(const float* __restrict__ c, const int* __restrict__ src, int Nc) {
    int gw   = (blockIdx.x * blockDim.x + threadIdx.x) >> 5;
    int lane = threadIdx.x & 31;
    if (gw >= Nc) return;
    int beg = g_row_start[gw], end = g_row_start[gw + 1];
    float4 A0 = make_float4(0.f, 0.f, 0.f, 0.f);
    float4 A1 = make_float4(0.f, 0.f, 0.f, 0.f);
    float d0 = 0.f, d1 = 0.f;
    if (beg < end) {
        float m = -1e30f;
        for (int i = beg + lane; i < end; i += 32) {
            float e = g_za[src[i]];
            e = e > 0.f ? e : 0.01f * e;
            m = fmaxf(m, e);
        }
        #pragma unroll
        for (int o = 16; o; o >>= 1) m = fmaxf(m, __shfl_xor_sync(0xffffffffu, m, o));
        int i = beg;
        for (; i + 2 <= end; i += 2) {
            int s0 = __ldg(&src[i]), s1 = __ldg(&src[i + 1]);
            float e0 = g_za[s0]; e0 = e0 > 0.f ? e0 : 0.01f * e0;
            float e1 = g_za[s1]; e1 = e1 > 0.f ? e1 : 0.01f * e1;
            float x0 = __expf(e0 - m), x1 = __expf(e1 - m);
            float4 z0 = *(const float4*)&g_z[(size_t)s0 * D + lane * 4];
            float4 z1 = *(const float4*)&g_z[(size_t)s1 * D + lane * 4];
            d0 += x0; d1 += x1;
            A0.x += x0 * z0.x; A0.y += x0 * z0.y; A0.z += x0 * z0.z; A0.w += x0 * z0.w;
            A1.x += x1 * z1.x; A1.y += x1 * z1.y; A1.z += x1 * z1.z; A1.w += x1 * z1.w;
        }
        if (i < end) {
            int s0 = __ldg(&src[i]);
            float e0 = g_za[s0]; e0 = e0 > 0.f ? e0 : 0.01f * e0;
            float x0 = __expf(e0 - m);
            float4 z0 = *(const float4*)&g_z[(size_t)s0 * D + lane * 4];
            d0 += x0;
            A0.x += x0 * z0.x; A0.y += x0 * z0.y; A0.z += x0 * z0.z; A0.w += x0 * z0.w;
        }
        float inv = 1.f / (d0 + d1);
        A0.x = (A0.x + A1.x) * inv; A0.y = (A0.y + A1.y) * inv;
        A0.z = (A0.z + A1.z) * inv; A0.w = (A0.w + A1.w) * inv;
    }
    float4 cv = *(const float4*)&c[(size_t)gw * D + lane * 4];
    float4 h;
    h.x = (A0.x > 0.f ? A0.x : __expf(A0.x) - 1.f) + cv.x;
    h.y = (A0.y > 0.f ? A0.y : __expf(A0.y) - 1.f) + cv.y;
    h.z = (A0.z > 0.f ? A0.z : __expf(A0.z) - 1.f) + cv.z;
    h.w = (A0.w > 0.f ? A0.w : __expf(A0.w) - 1.f) + cv.w;
    *(float4*)&g_hc[(size_t)gw * D + lane * 4] = h;
    float4 ht = make_float4(rnd_tf32(h.x), rnd_tf32(h.y), rnd_tf32(h.z), rnd_tf32(h.w));
    *(float4*)&g_hc_t[(size_t)gw * D + lane * 4] = ht;
}

// ---------------- hidden = relu(hc @ w1^T + b1), stored tf32-rounded ----------------
__global__ void __launch_bounds__(256, 2)
k_gemm_h1(const float* __restrict__ b1, int Nrows) {
    __shared__ float SA[3 * 2048], SB[3 * 2048];
    float acc[2][8][4] = {};
    const int row0 = blockIdx.x * 128;
    const int col0 = blockIdx.y * 128;
    mma_core_pipe<D>(g_hc_t, g_w1t, Nrows, row0, col0, acc, SA, SB);
    const int lane = threadIdx.x & 31, wid = threadIdx.x >> 5;
    const int wm = wid >> 1, wn = wid & 1;
    const int lr = lane >> 2, lc2 = (lane & 3) * 2;
    float2 bb[8];
    #pragma unroll
    for (int nf = 0; nf < 8; nf++)
        bb[nf] = *(const float2*)&b1[col0 + wn * 64 + nf * 8 + lc2];
    #pragma unroll
    for (int mf = 0; mf < 2; mf++)
        #pragma unroll
        for (int cp = 0; cp < 2; cp++) {
            int r = row0 + wm * 32 + mf * 16 + lr + cp * 8;
            if (r >= Nrows) continue;
            #pragma unroll
            for (int nf = 0; nf < 8; nf++) {
                float2 v;
                v.x = rnd_tf32(fmaxf(acc[mf][nf][cp * 2]     + bb[nf].x, 0.f));
                v.y = rnd_tf32(fmaxf(acc[mf][nf][cp * 2 + 1] + bb[nf].y, 0.f));
                *(float2*)&g_hidden[(size_t)r * HDIM + col0 + wn * 64 + nf * 8 + lc2] = v;
            }
        }
}

// --------- y = hidden @ w2^T + b2 + hc, LayerNorm -> out ---------
__global__ void __launch_bounds__(256, 2)
k_gemm_h2_ln(const float* __restrict__ b2,
             const float* __restrict__ lng, const float* __restrict__ lnb,
             float* __restrict__ out, int Nrows) {
    __shared__ float SA[3 * 2048], SB[3 * 2048];
    float acc[2][8][4] = {};
    const int row0 = blockIdx.x * 128;
    mma_core_pipe<HDIM>(g_hidden, g_w2t, Nrows, row0, 0, acc, SA, SB);
    // core ends with __syncthreads; SB reusable for LN partials
    float* part1 = SB;          // [2][128]
    float* part2 = SB + 256;    // [2][128]
    const int lane = threadIdx.x & 31, wid = threadIdx.x >> 5;
    const int wm = wid >> 1, wn = wid & 1;
    const int lr = lane >> 2, lc2 = (lane & 3) * 2;

    float2 bb[8], gg[8], be[8];
    #pragma unroll
    for (int nf = 0; nf < 8; nf++) {
        int cc = wn * 64 + nf * 8 + lc2;
        bb[nf] = *(const float2*)&b2[cc];
        gg[nf] = *(const float2*)&lng[cc];
        be[nf] = *(const float2*)&lnb[cc];
    }
    #pragma unroll
    for (int mf = 0; mf < 2; mf++)
        #pragma unroll
        for (int cp = 0; cp < 2; cp++) {
            int rl = wm * 32 + mf * 16 + lr + cp * 8;
            int r  = row0 + rl;
            bool ok = r < Nrows;
            float s1 = 0.f, s2 = 0.f;
            #pragma unroll
            for (int nf = 0; nf < 8; nf++) {
                float2 hv = ok ? *(const float2*)&g_hc[(size_t)r * D + wn * 64 + nf * 8 + lc2]
                               : make_float2(0.f, 0.f);
                float y0 = acc[mf][nf][cp * 2]     + bb[nf].x + hv.x;
                float y1 = acc[mf][nf][cp * 2 + 1] + bb[nf].y + hv.y;
                acc[mf][nf][cp * 2]     = y0;
                acc[mf][nf][cp * 2 + 1] = y1;
                s1 += y0 + y1;
                s2 += y0 * y0 + y1 * y1;
            }
            s1 += __shfl_xor_sync(0xffffffffu, s1, 1);
            s2 += __shfl_xor_sync(0xffffffffu, s2, 1);
            s1 += __shfl_xor_sync(0xffffffffu, s1, 2);
            s2 += __shfl_xor_sync(0xffffffffu, s2, 2);
            if ((lane & 3) == 0) {
                part1[wn * 128 + rl] = s1;
                part2[wn * 128 + rl] = s2;
            }
        }
    __syncthreads();
    #pragma unroll
    for (int mf = 0; mf < 2; mf++)
        #pragma unroll
        for (int cp = 0; cp < 2; cp++) {
            int rl = wm * 32 + mf * 16 + lr + cp * 8;
            int r  = row0 + rl;
            float s1 = part1[rl] + part1[128 + rl];
            float s2 = part2[rl] + part2[128 + rl];
            float mean = s1 * (1.f / D);
            float var  = s2 * (1.f / D) - mean * mean;
            float rstd = rsqrtf(var + LN_EPS);
            if (r >= Nrows) continue;
            #pragma unroll
            for (int nf = 0; nf < 8; nf++) {
                float2 v;
                v.x = (acc[mf][nf][cp * 2]     - mean) * rstd * gg[nf].x + be[nf].x;
                v.y = (acc[mf][nf][cp * 2 + 1] - mean) * rstd * gg[nf].y + be[nf].y;
                *(float2*)&out[(size_t)r * D + wn * 64 + nf * 8 + lc2] = v;
            }
        }
}

// ---------------- launch ----------------
extern "C" void kernel_launch(void* const* d_in, const int* in_sizes, int n_in,
                              void* d_out, int out_size) {
    const float* s      = (const float*)d_in[0];
    const float* c      = (const float*)d_in[1];
    const int*   src    = (const int*)d_in[2];
    const int*   dst    = (const int*)d_in[3];
    const float* Wfc    = (const float*)d_in[4];
    const float* a_attn = (const float*)d_in[5];
    const float* w1     = (const float*)d_in[6];
    const float* b1     = (const float*)d_in[7];
    const float* w2     = (const float*)d_in[8];
    const float* b2     = (const float*)d_in[9];
    const float* lng    = (const float*)d_in[10];
    const float* lnb    = (const float*)d_in[11];
    float* out = (float*)d_out;

    int Ns = in_sizes[0] / D;
    int Nc = in_sizes[1] / D;
    int E  = in_sizes[2];
    (void)n_in; (void)out_size;

    k_row_start<<<(E + 1 + 255) / 256, 256>>>(dst, E, Nc);
    k_cvt_w<<<(HDIM * D + 255) / 256, 256>>>(w1, w2);
    k_gemm_z<<<(Ns + 127) / 128, 256>>>(s, Wfc, a_attn, Ns);
    k_aggregate<<<(Nc * 32 + 255) / 256, 256>>>(c, src, Nc);
    {
        dim3 g((Nc + 127) / 128, HDIM / 128);
        k_gemm_h1<<<g, 256>>>(b1, Nc);
    }
    k_gemm_h2_ln<<<(Nc + 127) / 128, 256>>>(b2, lng, lnb, out, Nc);
}